// round 1
// baseline (speedup 1.0000x reference)
#include <cuda_runtime.h>
#include <cuda_bf16.h>

// out[e] = dot(src_feat[src_idx[e]], dst_feat[dst_idx[e]]), D=64 fp32.
// 16 lanes cooperate on one edge: each lane loads one float4 from each row
// (16 * 16B = 256B = the whole row, 2 cache lines, fully coalesced),
// then a 4-step shfl_xor reduction within the 16-lane group.

__global__ void __launch_bounds__(256) sddmm_dot64_kernel(
    const int* __restrict__ src_idx,
    const int* __restrict__ dst_idx,
    const float4* __restrict__ src_feat,   // [N, 16] float4
    const float4* __restrict__ dst_feat,   // [N, 16] float4
    float* __restrict__ out,
    int num_edges)
{
    int g = blockIdx.x * blockDim.x + threadIdx.x;
    int e = g >> 4;          // edge index (16 lanes per edge)
    int lane = g & 15;       // 0..15 within the group
    if (e >= num_edges) return;

    int s = __ldg(&src_idx[e]);
    int d = __ldg(&dst_idx[e]);

    float4 a = __ldg(&src_feat[(size_t)s * 16 + lane]);
    float4 b = __ldg(&dst_feat[(size_t)d * 16 + lane]);

    float p = a.x * b.x + a.y * b.y + a.z * b.z + a.w * b.w;

    // Reduce across the 16-lane group (groups are lane-aligned within the warp,
    // so xor-shuffles with offsets 8,4,2,1 stay inside the group).
    p += __shfl_xor_sync(0xffffffffu, p, 8);
    p += __shfl_xor_sync(0xffffffffu, p, 4);
    p += __shfl_xor_sync(0xffffffffu, p, 2);
    p += __shfl_xor_sync(0xffffffffu, p, 1);

    if (lane == 0) out[e] = p;
}

extern "C" void kernel_launch(void* const* d_in, const int* in_sizes, int n_in,
                              void* d_out, int out_size)
{
    const int*    src_idx  = (const int*)d_in[0];
    const int*    dst_idx  = (const int*)d_in[1];
    const float4* src_feat = (const float4*)d_in[2];
    const float4* dst_feat = (const float4*)d_in[3];
    float*        out      = (float*)d_out;

    int num_edges = in_sizes[0];          // E = 1,250,000

    int threads = 256;                    // 16 edges per block
    long long total_threads = (long long)num_edges * 16;
    int blocks = (int)((total_threads + threads - 1) / threads);

    sddmm_dot64_kernel<<<blocks, threads>>>(src_idx, dst_idx, src_feat, dst_feat,
                                            out, num_edges);
}

// round 2
// speedup vs baseline: 1.3059x; 1.3059x over previous
#include <cuda_runtime.h>
#include <cuda_bf16.h>

// out[e] = dot(src_feat[src_idx[e]], dst_feat[dst_idx[e]]), D=64 fp32.
//
// R2: 4 lanes per edge, each lane loads FOUR float4 from each gathered row
// (interleaved stride-4 so consecutive lanes touch consecutive 16B sectors).
// 8 independent LDG.128 per thread -> MLP=8 to hide L2-hit latency
// (previous version had MLP=2 and was latency-bound: issue=28.5%, all
// memory pipes < 45%).

__global__ void __launch_bounds__(256) sddmm_dot64_mlp8_kernel(
    const int* __restrict__ src_idx,
    const int* __restrict__ dst_idx,
    const float4* __restrict__ src_feat,   // [N, 16] float4
    const float4* __restrict__ dst_feat,   // [N, 16] float4
    float* __restrict__ out,
    int num_edges)
{
    int g = blockIdx.x * blockDim.x + threadIdx.x;
    int e = g >> 2;          // edge index (4 lanes per edge)
    int l = g & 3;           // 0..3 within the group
    if (e >= num_edges) return;

    int s = __ldg(&src_idx[e]);
    int d = __ldg(&dst_idx[e]);

    const float4* sa = src_feat + (size_t)s * 16 + l;
    const float4* db = dst_feat + (size_t)d * 16 + l;

    // 8 independent loads issued before any dependent math.
    float4 a0 = __ldg(sa + 0);
    float4 a1 = __ldg(sa + 4);
    float4 a2 = __ldg(sa + 8);
    float4 a3 = __ldg(sa + 12);
    float4 b0 = __ldg(db + 0);
    float4 b1 = __ldg(db + 4);
    float4 b2 = __ldg(db + 8);
    float4 b3 = __ldg(db + 12);

    float p0 = a0.x * b0.x + a0.y * b0.y + a0.z * b0.z + a0.w * b0.w;
    float p1 = a1.x * b1.x + a1.y * b1.y + a1.z * b1.z + a1.w * b1.w;
    float p2 = a2.x * b2.x + a2.y * b2.y + a2.z * b2.z + a2.w * b2.w;
    float p3 = a3.x * b3.x + a3.y * b3.y + a3.z * b3.z + a3.w * b3.w;
    float p = (p0 + p1) + (p2 + p3);

    // Reduce across the 4-lane group (groups are lane-aligned in the warp).
    p += __shfl_xor_sync(0xffffffffu, p, 2);
    p += __shfl_xor_sync(0xffffffffu, p, 1);

    if (l == 0) out[e] = p;   // lanes 0,4,8,... store 8 consecutive floats
}

extern "C" void kernel_launch(void* const* d_in, const int* in_sizes, int n_in,
                              void* d_out, int out_size)
{
    const int*    src_idx  = (const int*)d_in[0];
    const int*    dst_idx  = (const int*)d_in[1];
    const float4* src_feat = (const float4*)d_in[2];
    const float4* dst_feat = (const float4*)d_in[3];
    float*        out      = (float*)d_out;

    int num_edges = in_sizes[0];          // E = 1,250,000

    int threads = 256;                    // 64 edges per block
    long long total_threads = (long long)num_edges * 4;
    int blocks = (int)((total_threads + threads - 1) / threads);

    sddmm_dot64_mlp8_kernel<<<blocks, threads>>>(src_idx, dst_idx,
                                                 src_feat, dst_feat,
                                                 out, num_edges);
}

// round 7
// speedup vs baseline: 1.6121x; 1.2345x over previous
#include <cuda_runtime.h>
#include <cuda_bf16.h>

// out[e] = dot(src_feat[src_idx[e]], dst_feat[dst_idx[e]]), D=64 fp32.
//
// R3 (resubmission; prior attempts hit GPU-broker timeouts, never ran):
//  - 8 lanes per edge, 2 edges per thread.
//  - Each 8-lane group loads 8 consecutive float4 = exactly one 128B cache
//    line per LDG.128 warp-slice -> full-line L1 wavefronts (R2's stride-4
//    layout produced half-line wavefronts; L1 was the bottleneck @72%).
//  - 8 independent LDG.128 per thread (2 edges x 2 tables x 2 lines) keeps
//    MLP=8 to hide L2-hit latency.

__global__ void __launch_bounds__(256) sddmm_dot64_r3_kernel(
    const int* __restrict__ src_idx,
    const int* __restrict__ dst_idx,
    const float4* __restrict__ src_feat,   // [N, 16] float4
    const float4* __restrict__ dst_feat,   // [N, 16] float4
    float* __restrict__ out,
    int num_edges)
{
    int tid  = blockIdx.x * blockDim.x + threadIdx.x;
    int warp = tid >> 5;
    int w    = tid & 31;
    int sg   = w >> 3;     // 8-lane sub-group id within warp: 0..3
    int sl   = w & 7;      // lane within sub-group: 0..7

    // Each warp owns 8 consecutive edges; sub-group sg handles edges
    // base+sg (slot A) and base+sg+4 (slot B).
    int e0 = warp * 8 + sg;
    int e1 = e0 + 4;
    bool v0 = (e0 < num_edges);
    bool v1 = (e1 < num_edges);
    int e0c = v0 ? e0 : 0;     // clamp so loads stay in-bounds; stores predicated
    int e1c = v1 ? e1 : 0;

    int s0 = __ldg(&src_idx[e0c]);
    int d0 = __ldg(&dst_idx[e0c]);
    int s1 = __ldg(&src_idx[e1c]);
    int d1 = __ldg(&dst_idx[e1c]);

    const float4* ps0 = src_feat + (size_t)s0 * 16 + sl;
    const float4* pd0 = dst_feat + (size_t)d0 * 16 + sl;
    const float4* ps1 = src_feat + (size_t)s1 * 16 + sl;
    const float4* pd1 = dst_feat + (size_t)d1 * 16 + sl;

    // 8 independent loads, each warp-slice covering one full 128B line.
    float4 a0 = __ldg(ps0);        // edge0 src, line 0
    float4 a1 = __ldg(ps0 + 8);    // edge0 src, line 1
    float4 b0 = __ldg(pd0);        // edge0 dst, line 0
    float4 b1 = __ldg(pd0 + 8);    // edge0 dst, line 1
    float4 c0 = __ldg(ps1);        // edge1 src, line 0
    float4 c1 = __ldg(ps1 + 8);    // edge1 src, line 1
    float4 g0 = __ldg(pd1);        // edge1 dst, line 0
    float4 g1 = __ldg(pd1 + 8);    // edge1 dst, line 1

    float pA = a0.x * b0.x + a0.y * b0.y + a0.z * b0.z + a0.w * b0.w
             + a1.x * b1.x + a1.y * b1.y + a1.z * b1.z + a1.w * b1.w;
    float pB = c0.x * g0.x + c0.y * g0.y + c0.z * g0.z + c0.w * g0.w
             + c1.x * g1.x + c1.y * g1.y + c1.z * g1.z + c1.w * g1.w;

    // Reduce within each 8-lane group (xor 4,2,1 stays inside the group).
    pA += __shfl_xor_sync(0xffffffffu, pA, 4);
    pB += __shfl_xor_sync(0xffffffffu, pB, 4);
    pA += __shfl_xor_sync(0xffffffffu, pA, 2);
    pB += __shfl_xor_sync(0xffffffffu, pB, 2);
    pA += __shfl_xor_sync(0xffffffffu, pA, 1);
    pB += __shfl_xor_sync(0xffffffffu, pB, 1);

    if (sl == 0) {
        if (v0) out[e0] = pA;
        if (v1) out[e1] = pB;
    }
}

extern "C" void kernel_launch(void* const* d_in, const int* in_sizes, int n_in,
                              void* d_out, int out_size)
{
    const int*    src_idx  = (const int*)d_in[0];
    const int*    dst_idx  = (const int*)d_in[1];
    const float4* src_feat = (const float4*)d_in[2];
    const float4* dst_feat = (const float4*)d_in[3];
    float*        out      = (float*)d_out;

    int num_edges = in_sizes[0];          // E = 1,250,000

    int threads = 256;                    // 8 warps -> 64 edges per block
    int edges_per_block = 64;
    int blocks = (num_edges + edges_per_block - 1) / edges_per_block;

    sddmm_dot64_r3_kernel<<<blocks, threads>>>(src_idx, dst_idx,
                                               src_feat, dst_feat,
                                               out, num_edges);
}

// round 10
// speedup vs baseline: 1.6176x; 1.0035x over previous
#include <cuda_runtime.h>
#include <cuda_bf16.h>

// out[e] = dot(src_feat[src_idx[e]], dst_feat[dst_idx[e]]), D=64 fp32.
//
// R4 (resubmission; prior attempts hit GPU-broker timeouts, never ran):
// 8 lanes per edge (full 128B-line wavefronts, kept from R3),
// 3 edges per thread -> 12 independent LDG.128 per thread. More issuable
// work per latency exposure; __launch_bounds__(256,3) pins 3 CTAs/SM
// (~24 warps) so regs stay <= 85 without spilling.

__global__ void __launch_bounds__(256, 3) sddmm_dot64_r4_kernel(
    const int* __restrict__ src_idx,
    const int* __restrict__ dst_idx,
    const float4* __restrict__ src_feat,   // [N, 16] float4
    const float4* __restrict__ dst_feat,   // [N, 16] float4
    float* __restrict__ out,
    int num_edges)
{
    int tid  = blockIdx.x * blockDim.x + threadIdx.x;
    int warp = tid >> 5;
    int w    = tid & 31;
    int sg   = w >> 3;     // 8-lane sub-group id: 0..3
    int sl   = w & 7;      // lane within sub-group: 0..7

    // Each warp owns 12 consecutive edges; sub-group sg handles
    // base+sg, base+sg+4, base+sg+8.
    int base = warp * 12 + sg;

    int  e[3];
    bool v[3];
    int  s[3], d[3];
#pragma unroll
    for (int k = 0; k < 3; k++) {
        e[k] = base + 4 * k;
        v[k] = (e[k] < num_edges);
        int ec = v[k] ? e[k] : 0;          // clamp loads; stores predicated
        s[k] = __ldg(&src_idx[ec]);
        d[k] = __ldg(&dst_idx[ec]);
    }

    // 12 independent loads, each warp-slice = one full 128B line.
    float4 A0[3], A1[3], B0[3], B1[3];
#pragma unroll
    for (int k = 0; k < 3; k++) {
        const float4* ps = src_feat + (size_t)s[k] * 16 + sl;
        const float4* pd = dst_feat + (size_t)d[k] * 16 + sl;
        A0[k] = __ldg(ps);
        A1[k] = __ldg(ps + 8);
        B0[k] = __ldg(pd);
        B1[k] = __ldg(pd + 8);
    }

    float p[3];
#pragma unroll
    for (int k = 0; k < 3; k++) {
        p[k] = A0[k].x * B0[k].x + A0[k].y * B0[k].y
             + A0[k].z * B0[k].z + A0[k].w * B0[k].w
             + A1[k].x * B1[k].x + A1[k].y * B1[k].y
             + A1[k].z * B1[k].z + A1[k].w * B1[k].w;
    }

    // Reduce within each 8-lane group.
#pragma unroll
    for (int k = 0; k < 3; k++) {
        p[k] += __shfl_xor_sync(0xffffffffu, p[k], 4);
        p[k] += __shfl_xor_sync(0xffffffffu, p[k], 2);
        p[k] += __shfl_xor_sync(0xffffffffu, p[k], 1);
    }

    if (sl == 0) {
#pragma unroll
        for (int k = 0; k < 3; k++)
            if (v[k]) out[e[k]] = p[k];
    }
}

extern "C" void kernel_launch(void* const* d_in, const int* in_sizes, int n_in,
                              void* d_out, int out_size)
{
    const int*    src_idx  = (const int*)d_in[0];
    const int*    dst_idx  = (const int*)d_in[1];
    const float4* src_feat = (const float4*)d_in[2];
    const float4* dst_feat = (const float4*)d_in[3];
    float*        out      = (float*)d_out;

    int num_edges = in_sizes[0];          // E = 1,250,000

    int threads = 256;                    // 8 warps -> 96 edges per block
    int edges_per_block = 96;
    int blocks = (num_edges + edges_per_block - 1) / edges_per_block;

    sddmm_dot64_r4_kernel<<<blocks, threads>>>(src_idx, dst_idx,
                                               src_feat, dst_feat,
                                               out, num_edges);
}